// round 11
// baseline (speedup 1.0000x reference)
#include <cuda_runtime.h>

#define NPTS   4096
#define BATCH  8
#define NSAMP  32
#define R2     0.0625f
#define QPW    2
#define GD     28
#define GD3    (GD*GD*GD)
#define CAP    64
#define CAPC   24      // bucket slots per cell (P(overflow) ~ 1e-12)
#define JT     4
#define CPMAX  640
#define NITEMS (BATCH * NPTS / QPW)   // 16384
#define BGRID  128
#define BTHR   256
#define MGRID  296     // 148 SMs x 2 CTAs
#define MTHR   320     // 10 warps
#define NWARP  10

__device__ float4 xyz4g[BATCH * NPTS];
__device__ int    cellCnt[BATCH * GD3];
__device__ float4 bucketPts[BATCH * GD3 * CAPC];
__device__ int    bucketIdx[BATCH * GD3 * CAPC];
__device__ int    barCnt;      // monotonic (never reset) -> graph-replay safe
__device__ int    ticket;

__device__ __forceinline__ int cellc(float v) {
    int c = (int)floorf((v + 3.5f) * 4.0f);
    return min(GD - 1, max(0, c));
}

__device__ __forceinline__ unsigned long long pk2(float lo, float hi) {
    unsigned long long r;
    asm("mov.b64 %0, {%1, %2};" : "=l"(r) : "f"(lo), "f"(hi));
    return r;
}
__device__ __forceinline__ void ffma2(unsigned long long& d,
                                      unsigned long long a, unsigned long long b) {
    asm("fma.rn.f32x2 %0, %1, %2, %0;" : "+l"(d) : "l"(a), "l"(b));
}
__device__ __forceinline__ void fadd2(unsigned long long& d, unsigned long long a) {
    asm("add.rn.f32x2 %0, %0, %1;" : "+l"(d) : "l"(a));
}

// Lean build kernel: zero -> one monotonic barrier -> direct bucket scatter.
__global__ __launch_bounds__(BTHR) void lse_build(const float* __restrict__ xyz) {
    const int gt = blockIdx.x * BTHR + threadIdx.x;   // one point per thread

    if (gt == 0) ticket = 0;
    for (int i = gt; i < BATCH * GD3; i += BGRID * BTHR) cellCnt[i] = 0;

    __syncthreads();
    if (threadIdx.x == 0) {
        __threadfence();
        int old = atomicAdd(&barCnt, 1);
        int target = old - (old % BGRID) + BGRID;
        volatile int* p = &barCnt;
        while (*p < target) __nanosleep(64);
        __threadfence();
    }
    __syncthreads();

    float x = xyz[3*gt], y = xyz[3*gt+1], z = xyz[3*gt+2];
    float sq = fmaf(x, x, fmaf(y, y, z * z));
    float4 p4 = make_float4(2.0f*x, 2.0f*y, 2.0f*z, -sq);
    xyz4g[gt] = p4;
    int b = gt >> 12;
    int cid = (cellc(z) * GD + cellc(y)) * GD + cellc(x);
    int off = atomicAdd(&cellCnt[b * GD3 + cid], 1);
    off = min(off, CAPC - 1);                          // never fires; fault guard
    int pos = (b * GD3 + cid) * CAPC + off;
    bucketPts[pos] = p4;
    bucketIdx[pos] = gt & (NPTS - 1);
}

// Persistent main kernel: 296 CTAs x 320 thr (2/SM, 20 warps); warps steal
// 2-query items.
__global__ __launch_bounds__(MTHR, 2) void lse_main_kernel(
    const float* __restrict__ w1, const float* __restrict__ b1,
    const float* __restrict__ w2, const float* __restrict__ b2,
    float* __restrict__ out)
{
    __shared__ float  w2t[32 * 65];
    __shared__ float4 qp[NWARP][QPW];
    __shared__ int    nbrS[NWARP][QPW][CAP];            // bucket positions
    __shared__ int    cBase[NWARP][QPW][28];            // cid*CAPC per cell lane
    __shared__ unsigned short cPos[NWARP][CPMAX + 64];  // (q<<10)|(cl<<5)|i
    __shared__ __align__(16) float hbuf[NWARP][JT * 64];

    const int tid  = threadIdx.x;
    const int lane = tid & 31;
    const int w    = tid >> 5;

    for (int t = tid; t < 64 * 32; t += MTHR) {
        int o = t >> 5, i = t & 31;
        w2t[i * 65 + o] = w2[t];
    }
    __syncthreads();

    const unsigned below = (1u << lane) - 1u;
    const int dxl = lane % 3 - 1;
    const int dyl = (lane / 3) % 3 - 1;
    const int dzl = lane / 9 - 1;

    const float w1x = w1[3 * lane + 0];
    const float w1y = w1[3 * lane + 1];
    const float w1z = w1[3 * lane + 2];
    const float b1v = b1[lane];
    const unsigned long long bp = pk2(b2[lane], b2[lane + 32]);
    const unsigned long long zz = pk2(0.0f, 0.0f);

    unsigned long long w2p[32];
    #pragma unroll
    for (int i = 0; i < 32; i++)
        w2p[i] = pk2(w2t[i * 65 + lane], w2t[i * 65 + lane + 32]);

    for (;;) {
        int item;
        if (lane == 0) item = atomicAdd(&ticket, 1);
        item = __shfl_sync(0xffffffffu, item, 0);
        if (item >= NITEMS) break;
        const int b     = item >> 11;                  // 2048 items per batch
        const int nbase = (item & 2047) << 1;

        const float4* __restrict__ P   = xyz4g     + b * NPTS;
        const float4* __restrict__ SP  = bucketPts + (size_t)b * GD3 * CAPC;
        const int*    __restrict__ SI  = bucketIdx + (size_t)b * GD3 * CAPC;
        const int*    __restrict__ ccG = cellCnt   + b * GD3;

        float xn[QPW], yn[QPW], zn[QPW];
        int cnt0 = 0, cnt1 = 0;
        #pragma unroll
        for (int q = 0; q < QPW; q++) {
            float4 qn = P[nbase + q];
            xn[q] = 0.5f * qn.x;
            yn[q] = 0.5f * qn.y;
            zn[q] = 0.5f * qn.z;
            if (lane == 0) qp[w][q] = make_float4(xn[q], yn[q], zn[q], -qn.w - R2);
        }

        // ---- Phase 1a: 27-cell expansion with exact box-distance pruning
        int B = 0;
        #pragma unroll
        for (int q = 0; q < QPW; q++) {
            int gx = cellc(xn[q]) + dxl;
            int gy = cellc(yn[q]) + dyl;
            int gz = cellc(zn[q]) + dzl;
            bool cv = (lane < 27) & (gx >= 0) & (gx < GD) & (gy >= 0) & (gy < GD)
                                  & (gz >= 0) & (gz < GD);
            if (cv) {
                float lox = (gx == 0)      ? -1e30f : fmaf((float)gx, 0.25f, -3.5f);
                float hix = (gx == GD - 1) ?  1e30f : fmaf((float)gx, 0.25f, -3.25f);
                float loy = (gy == 0)      ? -1e30f : fmaf((float)gy, 0.25f, -3.5f);
                float hiy = (gy == GD - 1) ?  1e30f : fmaf((float)gy, 0.25f, -3.25f);
                float loz = (gz == 0)      ? -1e30f : fmaf((float)gz, 0.25f, -3.5f);
                float hiz = (gz == GD - 1) ?  1e30f : fmaf((float)gz, 0.25f, -3.25f);
                float dx = fmaxf(0.0f, fmaxf(lox - xn[q], xn[q] - hix));
                float dy = fmaxf(0.0f, fmaxf(loy - yn[q], yn[q] - hiy));
                float dz = fmaxf(0.0f, fmaxf(loz - zn[q], zn[q] - hiz));
                float d2 = fmaf(dx, dx, fmaf(dy, dy, dz * dz));
                cv = d2 <= R2 + 1e-5f;    // guard >> fp32 error: never wrongly prunes
            }
            int cc = 0, cid = 0;
            if (cv) {
                cid = (gz * GD + gy) * GD + gx;
                cc = ccG[cid];
            }
            cBase[w][q][min(lane, 27)] = cid * CAPC;
            int inc = cc;
            #pragma unroll
            for (int d = 1; d < 32; d <<= 1) {
                int u = __shfl_up_sync(0xffffffffu, inc, d);
                if (lane >= d) inc += u;
            }
            int base = B + (inc - cc);
            unsigned short tag0 = (unsigned short)((q << 10) | (lane << 5));
            for (int i = 0; i < cc; i++) {
                int idx = base + i;
                if (idx < CPMAX) cPos[w][idx] = tag0 + (unsigned short)i;
            }
            B += __shfl_sync(0xffffffffu, inc, 31);
        }
        const int T = min(B, CPMAX);
        __syncwarp();

        // ---- Phase 1b: software-pipelined gather, 2-ballot compaction
        {
            const int niter = (T + 31) >> 5;
            int tag = cPos[w][lane];
            int q   = (tag >> 10) & 1;
            int pos = (lane < T) ? (cBase[w][q][min((tag >> 5) & 31, 27)] + (tag & 31)) : 0;
            float4 p = SP[pos];
            for (int it = 0; it < niter; it++) {
                int tagN = 0, qN = 0, posN = 0;
                float4 pN = make_float4(0, 0, 0, 0);
                if (it + 1 < niter) {
                    int t2 = ((it + 1) << 5) + lane;
                    tagN = cPos[w][t2];
                    qN   = (tagN >> 10) & 1;
                    posN = (t2 < T) ? (cBase[w][qN][min((tagN >> 5) & 31, 27)] + (tagN & 31)) : 0;
                    pN   = SP[posN];
                }
                bool act = ((it << 5) + lane) < T;
                float4 Q = qp[w][q];
                float acc = fmaf(p.x, Q.x, fmaf(p.y, Q.y, fmaf(p.z, Q.z, p.w)));
                bool v = act && (acc > Q.w);
                unsigned vm = __ballot_sync(0xffffffffu, v);
                unsigned m0 = __ballot_sync(0xffffffffu, q != 0);
                unsigned msk0 = vm & ~m0;
                unsigned msk1 = vm &  m0;
                if (v) {
                    unsigned mym = (q == 0) ? msk0 : msk1;
                    int cq = (q == 0) ? cnt0 : cnt1;
                    int pn = cq + __popc(mym & below);
                    if (pn < CAP) nbrS[w][q][pn] = pos;
                }
                cnt0 += __popc(msk0);
                cnt1 += __popc(msk1);
                tag = tagN; q = qN; pos = posN; p = pN;
            }
        }
        __syncwarp();

        int cnt[QPW] = {cnt0, cnt1};

        // ---- Rare slow path: cnt > 32 -> keep 32 smallest ORIGINAL indices
        #pragma unroll
        for (int q = 0; q < QPW; q++) {
            if (cnt[q] > NSAMP) {
                int c = min(cnt[q], CAP);
                unsigned k0 = 0xffffffffu, k1 = 0xffffffffu;
                if (lane < c) {
                    int pos = nbrS[w][q][lane];
                    k0 = ((unsigned)SI[pos] << 20) | (unsigned)pos;
                }
                if (lane + 32 < c) {
                    int pos = nbrS[w][q][lane + 32];
                    k1 = ((unsigned)SI[pos] << 20) | (unsigned)pos;
                }
                for (int j = 0; j < NSAMP; j++) {
                    unsigned mn = min(k0, k1);
                    #pragma unroll
                    for (int d = 16; d >= 1; d >>= 1)
                        mn = min(mn, __shfl_xor_sync(0xffffffffu, mn, d));
                    if (lane == 0) nbrS[w][q][j] = (int)(mn & 0xFFFFFu);
                    if (k0 == mn) k0 = 0xffffffffu;
                    else if (k1 == mn) k1 = 0xffffffffu;
                }
                __syncwarp();
                cnt[q] = NSAMP;
            }
        }

        // ---- Phase 2: MLP + max pool; prefetched tiles, split accumulators
        float2* hrow2 = (float2*)&hbuf[w][0];
        #pragma unroll
        for (int q = 0; q < QPW; q++) {
            const int k = cnt[q];                       // 1..32
            const float qx = xn[q], qy = yn[q], qz = zn[q];
            float p0 = 0.0f, p1 = 0.0f;
            for (int j0 = 0; j0 < k; j0 += JT) {
                const int je = min(k, j0 + JT);
                int   posj[JT];
                float4 pv[JT];
                #pragma unroll
                for (int jj = 0; jj < JT; jj++)
                    posj[jj] = nbrS[w][q][min(j0 + jj, k - 1)];
                #pragma unroll
                for (int jj = 0; jj < JT; jj++)
                    pv[jj] = SP[posj[jj]];
                #pragma unroll
                for (int jj = 0; jj < JT; jj++) {
                    if (j0 + jj < je) {
                        float rx = fmaf(0.5f, pv[jj].x, -qx);
                        float ry = fmaf(0.5f, pv[jj].y, -qy);
                        float rz = fmaf(0.5f, pv[jj].z, -qz);
                        float h = fmaf(w1x, rx, fmaf(w1y, ry, fmaf(w1z, rz, b1v)));
                        h = fmaxf(h, 0.0f);
                        hrow2[jj * 32 + lane] = make_float2(h, h);
                    }
                }
                __syncwarp();
                #pragma unroll
                for (int jj = 0; jj < JT; jj++) {
                    if (j0 + jj < je) {
                        const ulonglong2* hr = (const ulonglong2*)&hbuf[w][jj * 64];
                        unsigned long long a0 = bp, a1 = zz, a2 = zz, a3 = zz;
                        #pragma unroll
                        for (int i = 0; i < 4; i++) {
                            ulonglong2 h0 = hr[4 * i    ];
                            ulonglong2 h1 = hr[4 * i + 1];
                            ulonglong2 h2 = hr[4 * i + 2];
                            ulonglong2 h3 = hr[4 * i + 3];
                            ffma2(a0, w2p[8 * i    ], h0.x);
                            ffma2(a1, w2p[8 * i + 1], h0.y);
                            ffma2(a2, w2p[8 * i + 2], h1.x);
                            ffma2(a3, w2p[8 * i + 3], h1.y);
                            ffma2(a0, w2p[8 * i + 4], h2.x);
                            ffma2(a1, w2p[8 * i + 5], h2.y);
                            ffma2(a2, w2p[8 * i + 6], h3.x);
                            ffma2(a3, w2p[8 * i + 7], h3.y);
                        }
                        fadd2(a0, a1);
                        fadd2(a2, a3);
                        fadd2(a0, a2);
                        float r0, r1;
                        asm("mov.b64 {%0, %1}, %2;" : "=f"(r0), "=f"(r1) : "l"(a0));
                        p0 = fmaxf(p0, fmaxf(r0, 0.0f));
                        p1 = fmaxf(p1, fmaxf(r1, 0.0f));
                    }
                }
                __syncwarp();
            }
            float* o = out + (size_t)(b * NPTS + nbase + q) * 65;
            o[lane]      = p0;
            o[lane + 32] = p1;
            if (lane == 0) o[64] = (float)k * (1.0f / 64.0f);
        }
    }
}

extern "C" void kernel_launch(void* const* d_in, const int* in_sizes, int n_in,
                              void* d_out, int out_size) {
    const float* xyz = (const float*)d_in[0];
    const float* w1  = (const float*)d_in[1];
    const float* b1  = (const float*)d_in[2];
    const float* w2  = (const float*)d_in[3];
    const float* b2  = (const float*)d_in[4];
    float* out = (float*)d_out;

    lse_build<<<BGRID, BTHR>>>(xyz);
    lse_main_kernel<<<MGRID, MTHR>>>(w1, b1, w2, b2, out);
}

// round 12
// speedup vs baseline: 1.3107x; 1.3107x over previous
#include <cuda_runtime.h>

#define NPTS   4096
#define BATCH  8
#define NSAMP  32
#define R2     0.0625f
#define QPW    4
#define GD     28
#define GD3    (GD*GD*GD)
#define CAP    64
#define CAPC   24      // bucket slots per cell (P(overflow) ~ 1e-12)
#define JT     4
#define CPMAX  768
#define NITEMS (BATCH * NPTS / QPW)   // 8192
#define BGRID  128
#define BTHR   256
#define MGRID  148
#define MTHR   512

__device__ float4 xyz4g[BATCH * NPTS];
__device__ int    cellCnt[BATCH * GD3];
__device__ float4 bucketPts[BATCH * GD3 * CAPC];
__device__ int    bucketIdx[BATCH * GD3 * CAPC];
__device__ int    barCnt;      // monotonic (never reset) -> graph-replay safe
__device__ int    ticket;

__device__ __forceinline__ int cellc(float v) {
    int c = (int)floorf((v + 3.5f) * 4.0f);
    return min(GD - 1, max(0, c));
}

__device__ __forceinline__ unsigned long long pk2(float lo, float hi) {
    unsigned long long r;
    asm("mov.b64 %0, {%1, %2};" : "=l"(r) : "f"(lo), "f"(hi));
    return r;
}
__device__ __forceinline__ void ffma2(unsigned long long& d,
                                      unsigned long long a, unsigned long long b) {
    asm("fma.rn.f32x2 %0, %1, %2, %0;" : "+l"(d) : "l"(a), "l"(b));
}
__device__ __forceinline__ void fadd2(unsigned long long& d, unsigned long long a) {
    asm("add.rn.f32x2 %0, %0, %1;" : "+l"(d) : "l"(a));
}

// Lean build kernel: zero -> one monotonic barrier -> direct bucket scatter.
__global__ __launch_bounds__(BTHR) void lse_build(const float* __restrict__ xyz) {
    const int gt = blockIdx.x * BTHR + threadIdx.x;   // one point per thread

    if (gt == 0) ticket = 0;
    for (int i = gt; i < BATCH * GD3; i += BGRID * BTHR) cellCnt[i] = 0;

    __syncthreads();
    if (threadIdx.x == 0) {
        __threadfence();
        int old = atomicAdd(&barCnt, 1);
        int target = old - (old % BGRID) + BGRID;
        volatile int* p = &barCnt;
        while (*p < target) __nanosleep(64);
        __threadfence();
    }
    __syncthreads();

    float x = xyz[3*gt], y = xyz[3*gt+1], z = xyz[3*gt+2];
    float sq = fmaf(x, x, fmaf(y, y, z * z));
    float4 p4 = make_float4(2.0f*x, 2.0f*y, 2.0f*z, -sq);
    xyz4g[gt] = p4;
    int b = gt >> 12;
    int cid = (cellc(z) * GD + cellc(y)) * GD + cellc(x);
    int off = atomicAdd(&cellCnt[b * GD3 + cid], 1);
    off = min(off, CAPC - 1);                          // never fires; fault guard
    int pos = (b * GD3 + cid) * CAPC + off;
    bucketPts[pos] = p4;
    bucketIdx[pos] = gt & (NPTS - 1);
}

// Persistent main kernel: 148 CTAs x 512 thr; warps steal 4-query items.
__global__ __launch_bounds__(MTHR, 1) void lse_main_kernel(
    const float* __restrict__ w1, const float* __restrict__ b1,
    const float* __restrict__ w2, const float* __restrict__ b2,
    float* __restrict__ out)
{
    __shared__ float  w2t[32 * 65];
    __shared__ float4 qp[16][QPW];
    __shared__ int    nbrS[16][QPW][CAP];              // bucket positions
    __shared__ int    cBase[16][QPW][28];              // cid*CAPC per cell lane
    __shared__ unsigned short cPos[16][CPMAX + 64];    // (q<<10)|(cl<<5)|i
    __shared__ __align__(16) float hbuf[16][JT * 32];  // h stored ONCE per lane

    const int tid  = threadIdx.x;
    const int lane = tid & 31;
    const int w    = tid >> 5;

    for (int t = tid; t < 64 * 32; t += MTHR) {
        int o = t >> 5, i = t & 31;
        w2t[i * 65 + o] = w2[t];
    }
    __syncthreads();

    const unsigned below = (1u << lane) - 1u;
    const int dxl = lane % 3 - 1;
    const int dyl = (lane / 3) % 3 - 1;
    const int dzl = lane / 9 - 1;

    const float w1x = w1[3 * lane + 0];
    const float w1y = w1[3 * lane + 1];
    const float w1z = w1[3 * lane + 2];
    const float b1v = b1[lane];
    const unsigned long long bpa = pk2(b2[lane], 0.0f);      // bias enters once
    const unsigned long long bpb = pk2(b2[lane + 32], 0.0f);
    const unsigned long long zz  = pk2(0.0f, 0.0f);

    // Input-channel-paired weights: w2pa[i] = (w2[lane][2i], w2[lane][2i+1])
    unsigned long long w2pa[16], w2pb[16];
    #pragma unroll
    for (int i = 0; i < 16; i++) {
        w2pa[i] = pk2(w2t[(2*i) * 65 + lane],      w2t[(2*i+1) * 65 + lane]);
        w2pb[i] = pk2(w2t[(2*i) * 65 + lane + 32], w2t[(2*i+1) * 65 + lane + 32]);
    }

    for (;;) {
        int item;
        if (lane == 0) item = atomicAdd(&ticket, 1);
        item = __shfl_sync(0xffffffffu, item, 0);
        if (item >= NITEMS) break;
        const int b     = item >> 10;
        const int nbase = (item & 1023) << 2;

        const float4* __restrict__ P   = xyz4g     + b * NPTS;
        const float4* __restrict__ SP  = bucketPts + (size_t)b * GD3 * CAPC;
        const int*    __restrict__ SI  = bucketIdx + (size_t)b * GD3 * CAPC;
        const int*    __restrict__ ccG = cellCnt   + b * GD3;

        float xn[QPW], yn[QPW], zn[QPW];
        int cnt0 = 0, cnt1 = 0, cnt2 = 0, cnt3 = 0;
        #pragma unroll
        for (int q = 0; q < QPW; q++) {
            float4 qn = P[nbase + q];
            xn[q] = 0.5f * qn.x;
            yn[q] = 0.5f * qn.y;
            zn[q] = 0.5f * qn.z;
            if (lane == 0) qp[w][q] = make_float4(xn[q], yn[q], zn[q], -qn.w - R2);
        }

        // ---- Phase 1a: 27-cell expansion with exact box-distance pruning
        int B = 0;
        #pragma unroll
        for (int q = 0; q < QPW; q++) {
            int gx = cellc(xn[q]) + dxl;
            int gy = cellc(yn[q]) + dyl;
            int gz = cellc(zn[q]) + dzl;
            bool cv = (lane < 27) & (gx >= 0) & (gx < GD) & (gy >= 0) & (gy < GD)
                                  & (gz >= 0) & (gz < GD);
            if (cv) {
                float lox = (gx == 0)      ? -1e30f : fmaf((float)gx, 0.25f, -3.5f);
                float hix = (gx == GD - 1) ?  1e30f : fmaf((float)gx, 0.25f, -3.25f);
                float loy = (gy == 0)      ? -1e30f : fmaf((float)gy, 0.25f, -3.5f);
                float hiy = (gy == GD - 1) ?  1e30f : fmaf((float)gy, 0.25f, -3.25f);
                float loz = (gz == 0)      ? -1e30f : fmaf((float)gz, 0.25f, -3.5f);
                float hiz = (gz == GD - 1) ?  1e30f : fmaf((float)gz, 0.25f, -3.25f);
                float dx = fmaxf(0.0f, fmaxf(lox - xn[q], xn[q] - hix));
                float dy = fmaxf(0.0f, fmaxf(loy - yn[q], yn[q] - hiy));
                float dz = fmaxf(0.0f, fmaxf(loz - zn[q], zn[q] - hiz));
                float d2 = fmaf(dx, dx, fmaf(dy, dy, dz * dz));
                cv = d2 <= R2 + 1e-5f;    // guard >> fp32 error: never wrongly prunes
            }
            int cc = 0, cid = 0;
            if (cv) {
                cid = (gz * GD + gy) * GD + gx;
                cc = ccG[cid];
            }
            cBase[w][q][min(lane, 27)] = cid * CAPC;
            int inc = cc;
            #pragma unroll
            for (int d = 1; d < 32; d <<= 1) {
                int u = __shfl_up_sync(0xffffffffu, inc, d);
                if (lane >= d) inc += u;
            }
            int base = B + (inc - cc);
            unsigned short tag0 = (unsigned short)((q << 10) | (lane << 5));
            for (int i = 0; i < cc; i++) {
                int idx = base + i;
                if (idx < CPMAX) cPos[w][idx] = tag0 + (unsigned short)i;
            }
            B += __shfl_sync(0xffffffffu, inc, 31);
        }
        const int T = min(B, CPMAX);
        __syncwarp();

        // ---- Phase 1b: software-pipelined gather, 3-ballot compaction
        {
            const int niter = (T + 31) >> 5;
            int tag = cPos[w][lane];
            int q   = (tag >> 10) & 3;
            int pos = (lane < T) ? (cBase[w][q][min((tag >> 5) & 31, 27)] + (tag & 31)) : 0;
            float4 p = SP[pos];
            for (int it = 0; it < niter; it++) {
                int tagN = 0, qN = 0, posN = 0;
                float4 pN = make_float4(0, 0, 0, 0);
                if (it + 1 < niter) {
                    int t2 = ((it + 1) << 5) + lane;
                    tagN = cPos[w][t2];
                    qN   = (tagN >> 10) & 3;
                    posN = (t2 < T) ? (cBase[w][qN][min((tagN >> 5) & 31, 27)] + (tagN & 31)) : 0;
                    pN   = SP[posN];
                }
                bool act = ((it << 5) + lane) < T;
                float4 Q = qp[w][q];
                float acc = fmaf(p.x, Q.x, fmaf(p.y, Q.y, fmaf(p.z, Q.z, p.w)));
                bool v = act && (acc > Q.w);
                unsigned vm = __ballot_sync(0xffffffffu, v);
                unsigned m0 = __ballot_sync(0xffffffffu, (q & 1) != 0);
                unsigned m1 = __ballot_sync(0xffffffffu, (q & 2) != 0);
                unsigned msk0 = vm & ~m0 & ~m1;
                unsigned msk1 = vm &  m0 & ~m1;
                unsigned msk2 = vm & ~m0 &  m1;
                unsigned msk3 = vm &  m0 &  m1;
                if (v) {
                    unsigned mym = (q == 0) ? msk0 : (q == 1) ? msk1 : (q == 2) ? msk2 : msk3;
                    int cq = (q == 0) ? cnt0 : (q == 1) ? cnt1 : (q == 2) ? cnt2 : cnt3;
                    int pn = cq + __popc(mym & below);
                    if (pn < CAP) nbrS[w][q][pn] = pos;
                }
                cnt0 += __popc(msk0);
                cnt1 += __popc(msk1);
                cnt2 += __popc(msk2);
                cnt3 += __popc(msk3);
                tag = tagN; q = qN; pos = posN; p = pN;
            }
        }
        __syncwarp();

        int cnt[QPW] = {cnt0, cnt1, cnt2, cnt3};

        // ---- Rare slow path: cnt > 32 -> keep 32 smallest ORIGINAL indices
        #pragma unroll
        for (int q = 0; q < QPW; q++) {
            if (cnt[q] > NSAMP) {
                int c = min(cnt[q], CAP);
                unsigned k0 = 0xffffffffu, k1 = 0xffffffffu;
                if (lane < c) {
                    int pos = nbrS[w][q][lane];
                    k0 = ((unsigned)SI[pos] << 20) | (unsigned)pos;
                }
                if (lane + 32 < c) {
                    int pos = nbrS[w][q][lane + 32];
                    k1 = ((unsigned)SI[pos] << 20) | (unsigned)pos;
                }
                for (int j = 0; j < NSAMP; j++) {
                    unsigned mn = min(k0, k1);
                    #pragma unroll
                    for (int d = 16; d >= 1; d >>= 1)
                        mn = min(mn, __shfl_xor_sync(0xffffffffu, mn, d));
                    if (lane == 0) nbrS[w][q][j] = (int)(mn & 0xFFFFFu);
                    if (k0 == mn) k0 = 0xffffffffu;
                    else if (k1 == mn) k1 = 0xffffffffu;
                }
                __syncwarp();
                cnt[q] = NSAMP;
            }
        }

        // ---- Phase 2: MLP + max pool; input-paired f32x2, h stored once
        #pragma unroll
        for (int q = 0; q < QPW; q++) {
            const int k = cnt[q];                       // 1..32
            const float qx = xn[q], qy = yn[q], qz = zn[q];
            float p0 = 0.0f, p1 = 0.0f;
            for (int j0 = 0; j0 < k; j0 += JT) {
                const int je = min(k, j0 + JT);
                int   posj[JT];
                float4 pv[JT];
                #pragma unroll
                for (int jj = 0; jj < JT; jj++)
                    posj[jj] = nbrS[w][q][min(j0 + jj, k - 1)];
                #pragma unroll
                for (int jj = 0; jj < JT; jj++)
                    pv[jj] = SP[posj[jj]];
                #pragma unroll
                for (int jj = 0; jj < JT; jj++) {
                    if (j0 + jj < je) {
                        float rx = fmaf(0.5f, pv[jj].x, -qx);
                        float ry = fmaf(0.5f, pv[jj].y, -qy);
                        float rz = fmaf(0.5f, pv[jj].z, -qz);
                        float h = fmaf(w1x, rx, fmaf(w1y, ry, fmaf(w1z, rz, b1v)));
                        hbuf[w][jj * 32 + lane] = fmaxf(h, 0.0f);
                    }
                }
                __syncwarp();
                #pragma unroll
                for (int jj = 0; jj < JT; jj++) {
                    if (j0 + jj < je) {
                        // 8 uniform LDS.128: pairs (h2i, h2i+1)
                        const ulonglong2* hr = (const ulonglong2*)&hbuf[w][jj * 32];
                        unsigned long long a0 = bpa, a1 = zz;   // channel lane
                        unsigned long long a2 = bpb, a3 = zz;   // channel lane+32
                        #pragma unroll
                        for (int i = 0; i < 8; i++) {
                            ulonglong2 hh = hr[i];
                            ffma2(a0, w2pa[2 * i    ], hh.x);
                            ffma2(a1, w2pa[2 * i + 1], hh.y);
                            ffma2(a2, w2pb[2 * i    ], hh.x);
                            ffma2(a3, w2pb[2 * i + 1], hh.y);
                        }
                        fadd2(a0, a1);
                        fadd2(a2, a3);
                        float e0, o0, e1, o1;
                        asm("mov.b64 {%0, %1}, %2;" : "=f"(e0), "=f"(o0) : "l"(a0));
                        asm("mov.b64 {%0, %1}, %2;" : "=f"(e1), "=f"(o1) : "l"(a2));
                        p0 = fmaxf(p0, fmaxf(e0 + o0, 0.0f));
                        p1 = fmaxf(p1, fmaxf(e1 + o1, 0.0f));
                    }
                }
                __syncwarp();
            }
            float* o = out + (size_t)(b * NPTS + nbase + q) * 65;
            o[lane]      = p0;
            o[lane + 32] = p1;
            if (lane == 0) o[64] = (float)k * (1.0f / 64.0f);
        }
    }
}

extern "C" void kernel_launch(void* const* d_in, const int* in_sizes, int n_in,
                              void* d_out, int out_size) {
    const float* xyz = (const float*)d_in[0];
    const float* w1  = (const float*)d_in[1];
    const float* b1  = (const float*)d_in[2];
    const float* w2  = (const float*)d_in[3];
    const float* b2  = (const float*)d_in[4];
    float* out = (float*)d_out;

    lse_build<<<BGRID, BTHR>>>(xyz);
    lse_main_kernel<<<MGRID, MTHR>>>(w1, b1, w2, b2, out);
}

// round 13
// speedup vs baseline: 1.3602x; 1.0377x over previous
#include <cuda_runtime.h>

#define NPTS   4096
#define BATCH  8
#define NSAMP  32
#define R2     0.0625f
#define QPW    4
#define GD     28
#define GD3    (GD*GD*GD)
#define CAP    64
#define CAPC   24      // bucket slots per cell (P(overflow) ~ 1e-12)
#define JT     4
#define CPMAX  768
#define NITEMS (BATCH * NPTS / QPW)   // 8192
#define BGRID  128
#define BTHR   256
#define MGRID  148
#define MTHR   512

__device__ float4 xyz4g[BATCH * NPTS];
__device__ int    cellCnt[BATCH * GD3];
__device__ float4 bucketPts[BATCH * GD3 * CAPC];
__device__ int    bucketIdx[BATCH * GD3 * CAPC];
__device__ int    barCnt;      // monotonic (never reset) -> graph-replay safe
__device__ int    ticket;

__device__ __forceinline__ int cellc(float v) {
    int c = (int)floorf((v + 3.5f) * 4.0f);
    return min(GD - 1, max(0, c));
}

__device__ __forceinline__ unsigned long long pk2(float lo, float hi) {
    unsigned long long r;
    asm("mov.b64 %0, {%1, %2};" : "=l"(r) : "f"(lo), "f"(hi));
    return r;
}
__device__ __forceinline__ void ffma2(unsigned long long& d,
                                      unsigned long long a, unsigned long long b) {
    asm("fma.rn.f32x2 %0, %1, %2, %0;" : "+l"(d) : "l"(a), "l"(b));
}
__device__ __forceinline__ void fadd2(unsigned long long& d, unsigned long long a) {
    asm("add.rn.f32x2 %0, %0, %1;" : "+l"(d) : "l"(a));
}

// mask of lanes [0, n) with n clamped to [0, 32]
__device__ __forceinline__ unsigned mask_lt(int n) {
    n = max(0, min(32, n));
    return (n == 32) ? 0xffffffffu : ((1u << n) - 1u);
}

// Lean build kernel: zero -> one monotonic barrier -> direct bucket scatter.
__global__ __launch_bounds__(BTHR) void lse_build(const float* __restrict__ xyz) {
    const int gt = blockIdx.x * BTHR + threadIdx.x;   // one point per thread

    if (gt == 0) ticket = 0;
    for (int i = gt; i < BATCH * GD3; i += BGRID * BTHR) cellCnt[i] = 0;

    __syncthreads();
    if (threadIdx.x == 0) {
        __threadfence();
        int old = atomicAdd(&barCnt, 1);
        int target = old - (old % BGRID) + BGRID;
        volatile int* p = &barCnt;
        while (*p < target) __nanosleep(64);
        __threadfence();
    }
    __syncthreads();

    float x = xyz[3*gt], y = xyz[3*gt+1], z = xyz[3*gt+2];
    float sq = fmaf(x, x, fmaf(y, y, z * z));
    float4 p4 = make_float4(2.0f*x, 2.0f*y, 2.0f*z, -sq);
    xyz4g[gt] = p4;
    int b = gt >> 12;
    int cid = (cellc(z) * GD + cellc(y)) * GD + cellc(x);
    int off = atomicAdd(&cellCnt[b * GD3 + cid], 1);
    off = min(off, CAPC - 1);                          // never fires; fault guard
    int pos = (b * GD3 + cid) * CAPC + off;
    bucketPts[pos] = p4;
    bucketIdx[pos] = gt & (NPTS - 1);
}

// Persistent main kernel: 148 CTAs x 512 thr; warps steal 4-query items.
__global__ __launch_bounds__(MTHR, 1) void lse_main_kernel(
    const float* __restrict__ w1, const float* __restrict__ b1,
    const float* __restrict__ w2, const float* __restrict__ b2,
    float* __restrict__ out)
{
    __shared__ float  w2t[32 * 65];
    __shared__ float4 qp[16][QPW];
    __shared__ int    nbrS[16][QPW][CAP];              // bucket positions
    __shared__ int    cBase[16][QPW][28];              // cid*CAPC per cell lane
    __shared__ unsigned short cPos[16][CPMAX + 64];    // (q<<10)|(cl<<5)|i
    __shared__ __align__(16) float hbuf[16][JT * 32];  // h stored once per lane

    const int tid  = threadIdx.x;
    const int lane = tid & 31;
    const int w    = tid >> 5;

    for (int t = tid; t < 64 * 32; t += MTHR) {
        int o = t >> 5, i = t & 31;
        w2t[i * 65 + o] = w2[t];
    }
    __syncthreads();

    const unsigned below = (1u << lane) - 1u;
    const int dxl = lane % 3 - 1;
    const int dyl = (lane / 3) % 3 - 1;
    const int dzl = lane / 9 - 1;

    const float w1x = w1[3 * lane + 0];
    const float w1y = w1[3 * lane + 1];
    const float w1z = w1[3 * lane + 2];
    const float b1v = b1[lane];
    const unsigned long long bpa = pk2(b2[lane], 0.0f);      // bias enters once
    const unsigned long long bpb = pk2(b2[lane + 32], 0.0f);
    const unsigned long long zz  = pk2(0.0f, 0.0f);

    // Input-channel-paired weights: w2pa[i] = (w2[lane][2i], w2[lane][2i+1])
    unsigned long long w2pa[16], w2pb[16];
    #pragma unroll
    for (int i = 0; i < 16; i++) {
        w2pa[i] = pk2(w2t[(2*i) * 65 + lane],      w2t[(2*i+1) * 65 + lane]);
        w2pb[i] = pk2(w2t[(2*i) * 65 + lane + 32], w2t[(2*i+1) * 65 + lane + 32]);
    }

    for (;;) {
        int item;
        if (lane == 0) item = atomicAdd(&ticket, 1);
        item = __shfl_sync(0xffffffffu, item, 0);
        if (item >= NITEMS) break;
        const int b     = item >> 10;
        const int nbase = (item & 1023) << 2;

        const float4* __restrict__ P   = xyz4g     + b * NPTS;
        const float4* __restrict__ SP  = bucketPts + (size_t)b * GD3 * CAPC;
        const int*    __restrict__ SI  = bucketIdx + (size_t)b * GD3 * CAPC;
        const int*    __restrict__ ccG = cellCnt   + b * GD3;

        float xn[QPW], yn[QPW], zn[QPW];
        int cnt0 = 0, cnt1 = 0, cnt2 = 0, cnt3 = 0;
        #pragma unroll
        for (int q = 0; q < QPW; q++) {
            float4 qn = P[nbase + q];
            xn[q] = 0.5f * qn.x;
            yn[q] = 0.5f * qn.y;
            zn[q] = 0.5f * qn.z;
            if (lane == 0) qp[w][q] = make_float4(xn[q], yn[q], zn[q], -qn.w - R2);
        }

        // ---- Phase 1a: 27-cell expansion, fractional-coordinate box pruning
        int B = 0;
        int bnd1 = 0, bnd2 = 0, bnd3 = 0;   // stream boundaries after q=0,1,2
        #pragma unroll
        for (int q = 0; q < QPW; q++) {
            int cx = cellc(xn[q]), cy = cellc(yn[q]), cz = cellc(zn[q]);
            // distance from query to adjacent cell walls along each axis
            float fx = xn[q] - fmaf((float)cx, 0.25f, -3.5f);
            float fy = yn[q] - fmaf((float)cy, 0.25f, -3.5f);
            float fz = zn[q] - fmaf((float)cz, 0.25f, -3.5f);
            int gx = cx + dxl, gy = cy + dyl, gz = cz + dzl;
            bool cv = (lane < 27) & (gx >= 0) & (gx < GD) & (gy >= 0) & (gy < GD)
                                  & (gz >= 0) & (gz < GD);
            float dx = (dxl < 0) ? fx : ((dxl > 0) ? (0.25f - fx) : 0.0f);
            float dy = (dyl < 0) ? fy : ((dyl > 0) ? (0.25f - fy) : 0.0f);
            float dz = (dzl < 0) ? fz : ((dzl > 0) ? (0.25f - fz) : 0.0f);
            float d2 = fmaf(dx, dx, fmaf(dy, dy, dz * dz));
            cv = cv && (d2 <= R2 + 1e-5f);   // guard >> fp32 error: never prunes wrongly
            int cc = 0, cid = 0;
            if (cv) {
                cid = (gz * GD + gy) * GD + gx;
                cc = ccG[cid];
            }
            cBase[w][q][min(lane, 27)] = cid * CAPC;
            int inc = cc;
            #pragma unroll
            for (int d = 1; d < 32; d <<= 1) {
                int u = __shfl_up_sync(0xffffffffu, inc, d);
                if (lane >= d) inc += u;
            }
            int base = B + (inc - cc);
            unsigned short tag0 = (unsigned short)((q << 10) | (lane << 5));
            for (int i = 0; i < cc; i++) {
                int idx = base + i;
                if (idx < CPMAX) cPos[w][idx] = tag0 + (unsigned short)i;
            }
            B += __shfl_sync(0xffffffffu, inc, 31);
            if (q == 0) bnd1 = B;
            if (q == 1) bnd2 = B;
            if (q == 2) bnd3 = B;
        }
        const int T = min(B, CPMAX);
        __syncwarp();

        // ---- Phase 1b: depth-2 pipelined gather, 1 ballot + boundary masks
        {
            const int niter = (T + 31) >> 5;
            int tagA = 0, posA = 0, tagB = 0, posB = 0;
            float4 pA = make_float4(0, 0, 0, 0), pB = pA;
            if (niter > 0) {
                tagA = cPos[w][lane];
                int qq = (tagA >> 10) & 3;
                posA = (lane < T) ? (cBase[w][qq][min((tagA >> 5) & 31, 27)] + (tagA & 31)) : 0;
                pA = SP[posA];
            }
            if (niter > 1) {
                int t2 = 32 + lane;
                tagB = cPos[w][t2];
                int qq = (tagB >> 10) & 3;
                posB = (t2 < T) ? (cBase[w][qq][min((tagB >> 5) & 31, 27)] + (tagB & 31)) : 0;
                pB = SP[posB];
            }
            for (int it = 0; it < niter; it++) {
                const int t0 = it << 5;
                int q = (tagA >> 10) & 3;
                float4 Q = qp[w][q];
                float acc = fmaf(pA.x, Q.x, fmaf(pA.y, Q.y, fmaf(pA.z, Q.z, pA.w)));
                bool v = ((t0 + lane) < T) && (acc > Q.w);
                unsigned vm = __ballot_sync(0xffffffffu, v);
                unsigned M1 = mask_lt(bnd1 - t0);
                unsigned M2 = mask_lt(bnd2 - t0);
                unsigned M3 = mask_lt(bnd3 - t0);
                unsigned msk0 = vm & M1;
                unsigned msk1 = vm & (M2 & ~M1);
                unsigned msk2 = vm & (M3 & ~M2);
                unsigned msk3 = vm & ~M3;
                if (v) {
                    unsigned mym = (q == 0) ? msk0 : (q == 1) ? msk1 : (q == 2) ? msk2 : msk3;
                    int cq = (q == 0) ? cnt0 : (q == 1) ? cnt1 : (q == 2) ? cnt2 : cnt3;
                    int pn = cq + __popc(mym & below);
                    if (pn < CAP) nbrS[w][q][pn] = posA;
                }
                cnt0 += __popc(msk0);
                cnt1 += __popc(msk1);
                cnt2 += __popc(msk2);
                cnt3 += __popc(msk3);
                // rotate pipeline
                tagA = tagB; posA = posB; pA = pB;
                if (it + 2 < niter) {
                    int t2 = ((it + 2) << 5) + lane;
                    tagB = cPos[w][t2];
                    int qq = (tagB >> 10) & 3;
                    posB = (t2 < T) ? (cBase[w][qq][min((tagB >> 5) & 31, 27)] + (tagB & 31)) : 0;
                    pB = SP[posB];
                }
            }
        }
        __syncwarp();

        int cnt[QPW] = {cnt0, cnt1, cnt2, cnt3};

        // ---- Rare slow path: cnt > 32 -> keep 32 smallest ORIGINAL indices
        #pragma unroll
        for (int q = 0; q < QPW; q++) {
            if (cnt[q] > NSAMP) {
                int c = min(cnt[q], CAP);
                unsigned k0 = 0xffffffffu, k1 = 0xffffffffu;
                if (lane < c) {
                    int pos = nbrS[w][q][lane];
                    k0 = ((unsigned)SI[pos] << 20) | (unsigned)pos;
                }
                if (lane + 32 < c) {
                    int pos = nbrS[w][q][lane + 32];
                    k1 = ((unsigned)SI[pos] << 20) | (unsigned)pos;
                }
                for (int j = 0; j < NSAMP; j++) {
                    unsigned mn = min(k0, k1);
                    #pragma unroll
                    for (int d = 16; d >= 1; d >>= 1)
                        mn = min(mn, __shfl_xor_sync(0xffffffffu, mn, d));
                    if (lane == 0) nbrS[w][q][j] = (int)(mn & 0xFFFFFu);
                    if (k0 == mn) k0 = 0xffffffffu;
                    else if (k1 == mn) k1 = 0xffffffffu;
                }
                __syncwarp();
                cnt[q] = NSAMP;
            }
        }

        // ---- Phase 2: MLP + max pool; input-paired f32x2, h stored once
        #pragma unroll
        for (int q = 0; q < QPW; q++) {
            const int k = cnt[q];                       // 1..32
            const float qx = xn[q], qy = yn[q], qz = zn[q];
            float p0 = 0.0f, p1 = 0.0f;
            for (int j0 = 0; j0 < k; j0 += JT) {
                const int je = min(k, j0 + JT);
                int   posj[JT];
                float4 pv[JT];
                #pragma unroll
                for (int jj = 0; jj < JT; jj++)
                    posj[jj] = nbrS[w][q][min(j0 + jj, k - 1)];
                #pragma unroll
                for (int jj = 0; jj < JT; jj++)
                    pv[jj] = SP[posj[jj]];
                #pragma unroll
                for (int jj = 0; jj < JT; jj++) {
                    if (j0 + jj < je) {
                        float rx = fmaf(0.5f, pv[jj].x, -qx);
                        float ry = fmaf(0.5f, pv[jj].y, -qy);
                        float rz = fmaf(0.5f, pv[jj].z, -qz);
                        float h = fmaf(w1x, rx, fmaf(w1y, ry, fmaf(w1z, rz, b1v)));
                        hbuf[w][jj * 32 + lane] = fmaxf(h, 0.0f);
                    }
                }
                __syncwarp();
                #pragma unroll
                for (int jj = 0; jj < JT; jj++) {
                    if (j0 + jj < je) {
                        // 8 uniform LDS.128: pairs (h2i, h2i+1)
                        const ulonglong2* hr = (const ulonglong2*)&hbuf[w][jj * 32];
                        unsigned long long a0 = bpa, a1 = zz;   // channel lane
                        unsigned long long a2 = bpb, a3 = zz;   // channel lane+32
                        #pragma unroll
                        for (int i = 0; i < 8; i++) {
                            ulonglong2 hh = hr[i];
                            ffma2(a0, w2pa[2 * i    ], hh.x);
                            ffma2(a1, w2pa[2 * i + 1], hh.y);
                            ffma2(a2, w2pb[2 * i    ], hh.x);
                            ffma2(a3, w2pb[2 * i + 1], hh.y);
                        }
                        fadd2(a0, a1);
                        fadd2(a2, a3);
                        float e0, o0, e1, o1;
                        asm("mov.b64 {%0, %1}, %2;" : "=f"(e0), "=f"(o0) : "l"(a0));
                        asm("mov.b64 {%0, %1}, %2;" : "=f"(e1), "=f"(o1) : "l"(a2));
                        p0 = fmaxf(p0, fmaxf(e0 + o0, 0.0f));
                        p1 = fmaxf(p1, fmaxf(e1 + o1, 0.0f));
                    }
                }
                __syncwarp();
            }
            float* o = out + (size_t)(b * NPTS + nbase + q) * 65;
            o[lane]      = p0;
            o[lane + 32] = p1;
            if (lane == 0) o[64] = (float)k * (1.0f / 64.0f);
        }
    }
}

extern "C" void kernel_launch(void* const* d_in, const int* in_sizes, int n_in,
                              void* d_out, int out_size) {
    const float* xyz = (const float*)d_in[0];
    const float* w1  = (const float*)d_in[1];
    const float* b1  = (const float*)d_in[2];
    const float* w2  = (const float*)d_in[3];
    const float* b2  = (const float*)d_in[4];
    float* out = (float*)d_out;

    lse_build<<<BGRID, BTHR>>>(xyz);
    lse_main_kernel<<<MGRID, MTHR>>>(w1, b1, w2, b2, out);
}

// round 14
// speedup vs baseline: 1.4452x; 1.0625x over previous
#include <cuda_runtime.h>

#define NPTS   4096
#define BATCH  8
#define NSAMP  32
#define R2     0.0625f
#define QPW    4
#define GD     28
#define GD3    (GD*GD*GD)
#define CAP    64
#define CAPC   24      // bucket slots per cell (P(overflow) ~ 1e-12)
#define KCH    16      // staged neighbors per chunk in phase 2
#define CPMAX  768
#define NITEMS (BATCH * NPTS / QPW)   // 8192
#define BGRID  128
#define BTHR   256
#define MGRID  148
#define MTHR   512

__device__ float4 xyz4g[BATCH * NPTS];
__device__ int    cellCnt[BATCH * GD3];
__device__ float4 bucketPts[BATCH * GD3 * CAPC];
__device__ int    bucketIdx[BATCH * GD3 * CAPC];
__device__ int    barCnt;      // monotonic (never reset) -> graph-replay safe
__device__ int    ticket;

__device__ __forceinline__ int cellc(float v) {
    int c = (int)floorf((v + 3.5f) * 4.0f);
    return min(GD - 1, max(0, c));
}

__device__ __forceinline__ unsigned long long pk2(float lo, float hi) {
    unsigned long long r;
    asm("mov.b64 %0, {%1, %2};" : "=l"(r) : "f"(lo), "f"(hi));
    return r;
}
__device__ __forceinline__ void ffma2(unsigned long long& d,
                                      unsigned long long a, unsigned long long b) {
    asm("fma.rn.f32x2 %0, %1, %2, %0;" : "+l"(d) : "l"(a), "l"(b));
}
__device__ __forceinline__ void fadd2(unsigned long long& d, unsigned long long a) {
    asm("add.rn.f32x2 %0, %0, %1;" : "+l"(d) : "l"(a));
}

// mask of lanes [0, n) with n clamped to [0, 32]
__device__ __forceinline__ unsigned mask_lt(int n) {
    n = max(0, min(32, n));
    return (n == 32) ? 0xffffffffu : ((1u << n) - 1u);
}

// Lean build kernel: zero -> one monotonic barrier -> direct bucket scatter.
__global__ __launch_bounds__(BTHR) void lse_build(const float* __restrict__ xyz) {
    const int gt = blockIdx.x * BTHR + threadIdx.x;   // one point per thread

    if (gt == 0) ticket = 0;
    for (int i = gt; i < BATCH * GD3; i += BGRID * BTHR) cellCnt[i] = 0;

    __syncthreads();
    if (threadIdx.x == 0) {
        __threadfence();
        int old = atomicAdd(&barCnt, 1);
        int target = old - (old % BGRID) + BGRID;
        volatile int* p = &barCnt;
        while (*p < target) __nanosleep(64);
        __threadfence();
    }
    __syncthreads();

    float x = xyz[3*gt], y = xyz[3*gt+1], z = xyz[3*gt+2];
    float sq = fmaf(x, x, fmaf(y, y, z * z));
    float4 p4 = make_float4(2.0f*x, 2.0f*y, 2.0f*z, -sq);
    xyz4g[gt] = p4;
    int b = gt >> 12;
    int cid = (cellc(z) * GD + cellc(y)) * GD + cellc(x);
    int off = atomicAdd(&cellCnt[b * GD3 + cid], 1);
    off = min(off, CAPC - 1);                          // never fires; fault guard
    int pos = (b * GD3 + cid) * CAPC + off;
    bucketPts[pos] = p4;
    bucketIdx[pos] = gt & (NPTS - 1);
}

// Persistent main kernel: 148 CTAs x 512 thr; warps steal 4-query items.
__global__ __launch_bounds__(MTHR, 1) void lse_main_kernel(
    const float* __restrict__ w1, const float* __restrict__ b1,
    const float* __restrict__ w2, const float* __restrict__ b2,
    float* __restrict__ out)
{
    __shared__ float  w2t[32 * 65];
    __shared__ float4 qp[16][QPW];
    __shared__ int    nbrS[16][QPW][CAP];              // bucket positions
    __shared__ int    cBase[16][QPW][28];              // cid*CAPC per cell lane
    __shared__ unsigned short cPos[16][CPMAX + 64];    // (q<<10)|(cl<<5)|i
    __shared__ __align__(16) float hbuf[16][KCH * 32]; // staged h rows

    const int tid  = threadIdx.x;
    const int lane = tid & 31;
    const int w    = tid >> 5;

    for (int t = tid; t < 64 * 32; t += MTHR) {
        int o = t >> 5, i = t & 31;
        w2t[i * 65 + o] = w2[t];
    }
    __syncthreads();

    const unsigned below = (1u << lane) - 1u;
    const int dxl = lane % 3 - 1;
    const int dyl = (lane / 3) % 3 - 1;
    const int dzl = lane / 9 - 1;

    const float w1x = w1[3 * lane + 0];
    const float w1y = w1[3 * lane + 1];
    const float w1z = w1[3 * lane + 2];
    const float b1v = b1[lane];
    const unsigned long long bpa = pk2(b2[lane], 0.0f);      // bias enters once
    const unsigned long long bpb = pk2(b2[lane + 32], 0.0f);
    const unsigned long long zz  = pk2(0.0f, 0.0f);

    // Input-channel-paired weights: w2pa[i] = (w2[lane][2i], w2[lane][2i+1])
    unsigned long long w2pa[16], w2pb[16];
    #pragma unroll
    for (int i = 0; i < 16; i++) {
        w2pa[i] = pk2(w2t[(2*i) * 65 + lane],      w2t[(2*i+1) * 65 + lane]);
        w2pb[i] = pk2(w2t[(2*i) * 65 + lane + 32], w2t[(2*i+1) * 65 + lane + 32]);
    }

    for (;;) {
        int item;
        if (lane == 0) item = atomicAdd(&ticket, 1);
        item = __shfl_sync(0xffffffffu, item, 0);
        if (item >= NITEMS) break;
        const int b     = item >> 10;
        const int nbase = (item & 1023) << 2;

        const float4* __restrict__ P   = xyz4g     + b * NPTS;
        const float4* __restrict__ SP  = bucketPts + (size_t)b * GD3 * CAPC;
        const int*    __restrict__ SI  = bucketIdx + (size_t)b * GD3 * CAPC;
        const int*    __restrict__ ccG = cellCnt   + b * GD3;

        float xn[QPW], yn[QPW], zn[QPW];
        int cnt0 = 0, cnt1 = 0, cnt2 = 0, cnt3 = 0;
        #pragma unroll
        for (int q = 0; q < QPW; q++) {
            float4 qn = P[nbase + q];
            xn[q] = 0.5f * qn.x;
            yn[q] = 0.5f * qn.y;
            zn[q] = 0.5f * qn.z;
            if (lane == 0) qp[w][q] = make_float4(xn[q], yn[q], zn[q], -qn.w - R2);
        }

        // ---- Phase 1a: 27-cell expansion, fractional-coordinate box pruning
        int B = 0;
        int bnd1 = 0, bnd2 = 0, bnd3 = 0;   // stream boundaries after q=0,1,2
        #pragma unroll
        for (int q = 0; q < QPW; q++) {
            int cx = cellc(xn[q]), cy = cellc(yn[q]), cz = cellc(zn[q]);
            // distance from query to adjacent cell walls along each axis
            float fx = xn[q] - fmaf((float)cx, 0.25f, -3.5f);
            float fy = yn[q] - fmaf((float)cy, 0.25f, -3.5f);
            float fz = zn[q] - fmaf((float)cz, 0.25f, -3.5f);
            int gx = cx + dxl, gy = cy + dyl, gz = cz + dzl;
            bool cv = (lane < 27) & (gx >= 0) & (gx < GD) & (gy >= 0) & (gy < GD)
                                  & (gz >= 0) & (gz < GD);
            float dx = (dxl < 0) ? fx : ((dxl > 0) ? (0.25f - fx) : 0.0f);
            float dy = (dyl < 0) ? fy : ((dyl > 0) ? (0.25f - fy) : 0.0f);
            float dz = (dzl < 0) ? fz : ((dzl > 0) ? (0.25f - fz) : 0.0f);
            float d2 = fmaf(dx, dx, fmaf(dy, dy, dz * dz));
            cv = cv && (d2 <= R2 + 1e-5f);   // guard >> fp32 error: never prunes wrongly
            int cc = 0, cid = 0;
            if (cv) {
                cid = (gz * GD + gy) * GD + gx;
                cc = ccG[cid];
            }
            cBase[w][q][min(lane, 27)] = cid * CAPC;
            int inc = cc;
            #pragma unroll
            for (int d = 1; d < 32; d <<= 1) {
                int u = __shfl_up_sync(0xffffffffu, inc, d);
                if (lane >= d) inc += u;
            }
            int base = B + (inc - cc);
            unsigned short tag0 = (unsigned short)((q << 10) | (lane << 5));
            for (int i = 0; i < cc; i++) {
                int idx = base + i;
                if (idx < CPMAX) cPos[w][idx] = tag0 + (unsigned short)i;
            }
            B += __shfl_sync(0xffffffffu, inc, 31);
            if (q == 0) bnd1 = B;
            if (q == 1) bnd2 = B;
            if (q == 2) bnd3 = B;
        }
        const int T = min(B, CPMAX);
        __syncwarp();

        // ---- Phase 1b: depth-2 pipelined gather, 1 ballot + boundary masks
        {
            const int niter = (T + 31) >> 5;
            int tagA = 0, posA = 0, tagB = 0, posB = 0;
            float4 pA = make_float4(0, 0, 0, 0), pB = pA;
            if (niter > 0) {
                tagA = cPos[w][lane];
                int qq = (tagA >> 10) & 3;
                posA = (lane < T) ? (cBase[w][qq][min((tagA >> 5) & 31, 27)] + (tagA & 31)) : 0;
                pA = SP[posA];
            }
            if (niter > 1) {
                int t2 = 32 + lane;
                tagB = cPos[w][t2];
                int qq = (tagB >> 10) & 3;
                posB = (t2 < T) ? (cBase[w][qq][min((tagB >> 5) & 31, 27)] + (tagB & 31)) : 0;
                pB = SP[posB];
            }
            for (int it = 0; it < niter; it++) {
                const int t0 = it << 5;
                int q = (tagA >> 10) & 3;
                float4 Q = qp[w][q];
                float acc = fmaf(pA.x, Q.x, fmaf(pA.y, Q.y, fmaf(pA.z, Q.z, pA.w)));
                bool v = ((t0 + lane) < T) && (acc > Q.w);
                unsigned vm = __ballot_sync(0xffffffffu, v);
                unsigned M1 = mask_lt(bnd1 - t0);
                unsigned M2 = mask_lt(bnd2 - t0);
                unsigned M3 = mask_lt(bnd3 - t0);
                unsigned msk0 = vm & M1;
                unsigned msk1 = vm & (M2 & ~M1);
                unsigned msk2 = vm & (M3 & ~M2);
                unsigned msk3 = vm & ~M3;
                if (v) {
                    unsigned mym = (q == 0) ? msk0 : (q == 1) ? msk1 : (q == 2) ? msk2 : msk3;
                    int cq = (q == 0) ? cnt0 : (q == 1) ? cnt1 : (q == 2) ? cnt2 : cnt3;
                    int pn = cq + __popc(mym & below);
                    if (pn < CAP) nbrS[w][q][pn] = posA;
                }
                cnt0 += __popc(msk0);
                cnt1 += __popc(msk1);
                cnt2 += __popc(msk2);
                cnt3 += __popc(msk3);
                // rotate pipeline
                tagA = tagB; posA = posB; pA = pB;
                if (it + 2 < niter) {
                    int t2 = ((it + 2) << 5) + lane;
                    tagB = cPos[w][t2];
                    int qq = (tagB >> 10) & 3;
                    posB = (t2 < T) ? (cBase[w][qq][min((tagB >> 5) & 31, 27)] + (tagB & 31)) : 0;
                    pB = SP[posB];
                }
            }
        }
        __syncwarp();

        int cnt[QPW] = {cnt0, cnt1, cnt2, cnt3};

        // ---- Rare slow path: cnt > 32 -> keep 32 smallest ORIGINAL indices
        #pragma unroll
        for (int q = 0; q < QPW; q++) {
            if (cnt[q] > NSAMP) {
                int c = min(cnt[q], CAP);
                unsigned k0 = 0xffffffffu, k1 = 0xffffffffu;
                if (lane < c) {
                    int pos = nbrS[w][q][lane];
                    k0 = ((unsigned)SI[pos] << 20) | (unsigned)pos;
                }
                if (lane + 32 < c) {
                    int pos = nbrS[w][q][lane + 32];
                    k1 = ((unsigned)SI[pos] << 20) | (unsigned)pos;
                }
                for (int j = 0; j < NSAMP; j++) {
                    unsigned mn = min(k0, k1);
                    #pragma unroll
                    for (int d = 16; d >= 1; d >>= 1)
                        mn = min(mn, __shfl_xor_sync(0xffffffffu, mn, d));
                    if (lane == 0) nbrS[w][q][j] = (int)(mn & 0xFFFFFu);
                    if (k0 == mn) k0 = 0xffffffffu;
                    else if (k1 == mn) k1 = 0xffffffffu;
                }
                __syncwarp();
                cnt[q] = NSAMP;
            }
        }

        // ---- Phase 2: stage-all then accumulate-all (max ILP, min syncs)
        #pragma unroll
        for (int q = 0; q < QPW; q++) {
            const int k = cnt[q];                       // 1..32
            const float qx = xn[q], qy = yn[q], qz = zn[q];
            float p0 = 0.0f, p1 = 0.0f;
            for (int c0 = 0; c0 < k; c0 += KCH) {       // 1 chunk for k<=16
                const int ce = min(k, c0 + KCH);
                // Stage h rows [c0, ce) into hbuf (4-wide LDG prefetch)
                for (int j0 = c0; j0 < ce; j0 += 4) {
                    const int je = min(ce, j0 + 4);
                    int   posj[4];
                    float4 pv[4];
                    #pragma unroll
                    for (int jj = 0; jj < 4; jj++)
                        posj[jj] = nbrS[w][q][min(j0 + jj, k - 1)];
                    #pragma unroll
                    for (int jj = 0; jj < 4; jj++)
                        pv[jj] = SP[posj[jj]];
                    #pragma unroll
                    for (int jj = 0; jj < 4; jj++) {
                        if (j0 + jj < je) {
                            float rx = fmaf(0.5f, pv[jj].x, -qx);
                            float ry = fmaf(0.5f, pv[jj].y, -qy);
                            float rz = fmaf(0.5f, pv[jj].z, -qz);
                            float h = fmaf(w1x, rx, fmaf(w1y, ry, fmaf(w1z, rz, b1v)));
                            hbuf[w][(j0 + jj - c0) * 32 + lane] = fmaxf(h, 0.0f);
                        }
                    }
                }
                __syncwarp();
                // Accumulate all staged rows: independent iterations -> deep ILP
                #pragma unroll 2
                for (int j = c0; j < ce; j++) {
                    const ulonglong2* hr = (const ulonglong2*)&hbuf[w][(j - c0) * 32];
                    unsigned long long a0 = bpa, a1 = zz;   // channel lane
                    unsigned long long a2 = bpb, a3 = zz;   // channel lane+32
                    #pragma unroll
                    for (int i = 0; i < 8; i++) {
                        ulonglong2 hh = hr[i];
                        ffma2(a0, w2pa[2 * i    ], hh.x);
                        ffma2(a1, w2pa[2 * i + 1], hh.y);
                        ffma2(a2, w2pb[2 * i    ], hh.x);
                        ffma2(a3, w2pb[2 * i + 1], hh.y);
                    }
                    fadd2(a0, a1);
                    fadd2(a2, a3);
                    float e0, o0, e1, o1;
                    asm("mov.b64 {%0, %1}, %2;" : "=f"(e0), "=f"(o0) : "l"(a0));
                    asm("mov.b64 {%0, %1}, %2;" : "=f"(e1), "=f"(o1) : "l"(a2));
                    p0 = fmaxf(p0, fmaxf(e0 + o0, 0.0f));
                    p1 = fmaxf(p1, fmaxf(e1 + o1, 0.0f));
                }
                __syncwarp();
            }
            float* o = out + (size_t)(b * NPTS + nbase + q) * 65;
            o[lane]      = p0;
            o[lane + 32] = p1;
            if (lane == 0) o[64] = (float)k * (1.0f / 64.0f);
        }
    }
}

extern "C" void kernel_launch(void* const* d_in, const int* in_sizes, int n_in,
                              void* d_out, int out_size) {
    const float* xyz = (const float*)d_in[0];
    const float* w1  = (const float*)d_in[1];
    const float* b1  = (const float*)d_in[2];
    const float* w2  = (const float*)d_in[3];
    const float* b2  = (const float*)d_in[4];
    float* out = (float*)d_out;

    lse_build<<<BGRID, BTHR>>>(xyz);
    lse_main_kernel<<<MGRID, MTHR>>>(w1, b1, w2, b2, out);
}